// round 14
// baseline (speedup 1.0000x reference)
#include <cuda_runtime.h>
#include <cuda_fp16.h>
#include <cstdint>

// out[b,h,i,j] = scores[b,h,i,j] + sum_d q[b,h,i,d] * E[(j-i)+4096, d]
// B=2,H=16,S=2048,D=64.
//
// 64x128 (i,j) tile. G[i,r] = Q(64x64) . E_rows(192x64)^T, j = r + i - 63.
// fp16 mma.sync m16n8k16, disjoint warp partition (R12): warp (ng,mh) owns
// n-tiles [6ng,6ng+5] x m-tiles {2mh,2mh+1}; invalid slots computed (in-bounds
// reads) but never stored. Q/E pre-converted to fp16 scratch (vectorized
// pre-kernel) and staged with ONE cp.async.bulk each.
// R14 change vs R12: scores tile no longer staged through SMEM. A one-
// instruction-per-thread prefetch.global.L2 sweep at kernel entry (256
// threads x 128B sector = the whole 64x512B tile) warms L2 during the
// mainloop; the epilogue LDGs scores directly (L2 hit, 4-wide MLP). Removes
// the TMA-write + LDS-read phases of sS, 32KB SMEM, and holds no registers
// during the mainloop -> 3 CTAs/SM preserved (R13 lesson: occupancy binds).

#define S_LEN 2048
#define TI 64
#define TJ 128
#define ER 192
#define PW 36            // Q/E pitch (u32); mainloop banks 4g+t bijective
#define SGP 148          // sG pitch (floats)

#define SMEM_QE_U32  (TI * PW + ER * PW)     // 9216
#define SMEM_G_U32   (TI * SGP)              // 9472 (aliases QE region)
#define SMEM_UNION_U32 (SMEM_G_U32 > SMEM_QE_U32 ? SMEM_G_U32 : SMEM_QE_U32)
#define SMEM_U32 (SMEM_UNION_U32 + 8)
#define SMEM_BYTES (SMEM_U32 * 4)            // 37920

// fp16 scratch, pitch 36 u32/row (cols 32..35 pad, never read)
__device__ uint32_t g_qsc[32 * 2048 * PW];   // 9.4 MB
__device__ uint32_t g_esc[8192 * PW];        // 1.2 MB

__device__ __forceinline__ uint32_t smem_u32p(const void* p) {
    uint32_t a;
    asm("{ .reg .u64 t; cvta.to.shared.u64 t, %1; cvt.u32.u64 %0, t; }"
        : "=r"(a) : "l"(p));
    return a;
}

#define MBARRIER_INIT(mbar, cnt) \
    asm volatile("mbarrier.init.shared.b64 [%0], %1;" \
                 :: "r"((uint32_t)(mbar)), "r"((uint32_t)(cnt)) : "memory")
#define MBARRIER_EXPECT_TX(mbar, bytes) \
    asm volatile("mbarrier.arrive.expect_tx.shared.b64 _, [%0], %1;" \
                 :: "r"((uint32_t)(mbar)), "r"((uint32_t)(bytes)) : "memory")
#define MBARRIER_WAIT_PARITY(mbar, par) do {                                   \
    asm volatile(                                                              \
        "{\n\t.reg .pred P1;\n\t"                                              \
        "WAIT_LOOP_%=:\n\t"                                                    \
        "mbarrier.try_wait.parity.acquire.cta.shared::cta.b64 P1, [%0], %1, 0x989680;\n\t" \
        "@P1 bra.uni WAIT_DONE_%=;\n\t"                                        \
        "bra.uni WAIT_LOOP_%=;\n\t"                                            \
        "WAIT_DONE_%=:\n\t}"                                                   \
        :: "r"((uint32_t)(mbar)), "r"((uint32_t)(par)) : "memory");            \
} while (0)
#define FENCE_PROXY_ASYNC() asm volatile("fence.proxy.async.shared::cta;" ::: "memory")

#define BULK_G2S(dst, src, bytes, mbar) \
    asm volatile("cp.async.bulk.shared::cluster.global.mbarrier::complete_tx::bytes " \
                 "[%0], [%1], %2, [%3];" \
                 :: "r"((uint32_t)(dst)), "l"(src), "r"((uint32_t)(bytes)), \
                    "r"((uint32_t)(mbar)) : "memory")

__device__ __forceinline__ void mma_f16(float* c,
                                        uint32_t a0, uint32_t a1,
                                        uint32_t a2, uint32_t a3,
                                        uint32_t b0, uint32_t b1) {
    asm volatile(
        "mma.sync.aligned.m16n8k16.row.col.f32.f16.f16.f32 "
        "{%0,%1,%2,%3}, {%4,%5,%6,%7}, {%8,%9}, {%0,%1,%2,%3};"
        : "+f"(c[0]), "+f"(c[1]), "+f"(c[2]), "+f"(c[3])
        : "r"(a0), "r"(a1), "r"(a2), "r"(a3), "r"(b0), "r"(b1));
}

__device__ __forceinline__ uint32_t pack_h2(float lo, float hi) {
    __half2 h = __floats2half2_rn(lo, hi);
    return *(uint32_t*)&h;
}

// ---- Pre-kernel: fp32 -> fp16 scratch (pitch 36), vectorized x4 ----
#define Q_G4 (32 * 2048 * 8)   // groups of 4 u32 (8 halfs) for Q
#define E_G4 (8192 * 8)
__global__ __launch_bounds__(256)
void convert_kernel(const float* __restrict__ query,
                    const float* __restrict__ rel)
{
    int idx = blockIdx.x * 256 + threadIdx.x;
    if (idx < Q_G4) {
        int row = idx >> 3, c4 = (idx & 7) << 2;          // u32 col, x4
        const float* src = query + (size_t)row * 64 + (c4 << 1);
        float4 v0 = *(const float4*)(src);
        float4 v1 = *(const float4*)(src + 4);
        uint4 o;
        o.x = pack_h2(v0.x, v0.y); o.y = pack_h2(v0.z, v0.w);
        o.z = pack_h2(v1.x, v1.y); o.w = pack_h2(v1.z, v1.w);
        *(uint4*)(g_qsc + row * PW + c4) = o;
    } else if (idx < Q_G4 + E_G4) {
        int e = idx - Q_G4;
        int row = e >> 3, c4 = (e & 7) << 2;
        const float* src = rel + (size_t)row * 64 + (c4 << 1);
        float4 v0 = *(const float4*)(src);
        float4 v1 = *(const float4*)(src + 4);
        uint4 o;
        o.x = pack_h2(v0.x, v0.y); o.y = pack_h2(v0.z, v0.w);
        o.z = pack_h2(v1.x, v1.y); o.w = pack_h2(v1.z, v1.w);
        *(uint4*)(g_esc + row * PW + c4) = o;
    }
}

__global__ __launch_bounds__(256, 3)
void relpos_mma(const float* __restrict__ scores,
                float* __restrict__ out)
{
    extern __shared__ uint32_t smem[];
    uint32_t* Qs = smem;                       // [64][PW] packed half2
    uint32_t* Es = Qs + TI * PW;               // [192][PW]
    float*    sG = (float*)smem;               // [64][SGP] aliases Qs/Es
    uint32_t* bars = smem + SMEM_UNION_U32;
    const uint32_t barQE = smem_u32p(bars);

    const int tid  = threadIdx.x;
    const int wid  = tid >> 5;
    const int lane = tid & 31;
    const int gid  = lane >> 2;
    const int tig  = lane & 3;
    const int bh = blockIdx.z;
    const int i0 = blockIdx.y * TI;
    const int j0 = blockIdx.x * TJ;
    const size_t gbase = ((size_t)bh * S_LEN + i0) * S_LEN + j0;

    if (tid == 0) {
        MBARRIER_INIT(barQE, 1);
        FENCE_PROXY_ASYNC();
        MBARRIER_EXPECT_TX(barQE, (TI + ER) * PW * 4);
    }

    // ---- L2 prefetch of the scores tile: 256 threads x one 128B sector
    //      (64 rows x 4 sectors). No registers held, no SMEM; the mainloop
    //      provides the latency cover, the epilogue LDGs then hit L2.
    {
        const int r = tid >> 2;            // 0..63
        const int s = tid & 3;             // 0..3
        const float* p = scores + gbase + (size_t)r * S_LEN + 32 * s;
        asm volatile("prefetch.global.L2 [%0];" :: "l"(p));
    }

    __syncthreads();   // barrier init visible before waits

    if (tid == 0) {
        // Q + E tiles: single contiguous bulk copies from fp16 scratch
        const uint32_t* qsrc = g_qsc + ((size_t)bh * S_LEN + i0) * PW;
        BULK_G2S(smem_u32p(Qs), qsrc, TI * PW * 4, barQE);
        const int rBase = 4096 - 63 + (j0 - i0);   // [2049,5953]; +191 < 8192
        const uint32_t* esrc = g_esc + (size_t)rBase * PW;
        BULK_G2S(smem_u32p(Es), esrc, ER * PW * 4, barQE);
    }

    // ---- Wait Q/E, then band mainloop ----
    MBARRIER_WAIT_PARITY(barQE, 0);

    // warp (ng, mh): n-tiles 6ng..6ng+5, m-tiles {2mh, 2mh+1}
    const int ng = wid & 3;
    const int mh = wid >> 2;

    float acc[12][4];
    #pragma unroll
    for (int s = 0; s < 12; ++s) {
        acc[s][0] = 0.f; acc[s][1] = 0.f; acc[s][2] = 0.f; acc[s][3] = 0.f;
    }

    const uint32_t* aP0 = Qs + (32 * mh + gid) * PW + tig;       // m-tile 2mh
    const uint32_t* aP1 = aP0 + 16 * PW;                         // m-tile 2mh+1
    const uint32_t* bP  = Es + (48 * ng + gid) * PW + tig;

    #pragma unroll
    for (int k = 0; k < 4; ++k) {              // K = 64, 16 per MMA
        uint32_t a00 = aP0[0], a01 = aP0[8 * PW], a02 = aP0[4], a03 = aP0[8 * PW + 4];
        uint32_t a10 = aP1[0], a11 = aP1[8 * PW], a12 = aP1[4], a13 = aP1[8 * PW + 4];
        #pragma unroll
        for (int t = 0; t < 6; ++t) {
            const uint32_t* bp = bP + t * (8 * PW);
            uint32_t b0 = bp[0], b1 = bp[4];
            mma_f16(acc[t],     a00, a01, a02, a03, b0, b1);
            mma_f16(acc[6 + t], a10, a11, a12, a13, b0, b1);
        }
        aP0 += 8; aP1 += 8; bP += 8;           // +16 halfs
    }
    __syncthreads();                           // Q/E dead: sG may overwrite

    // ---- Band store (valid slots only; warp-uniform branch) ----
    // slot (mt, t): mi = 2mh+mt, n = 6ng+t; valid iff 6-2mi <= n <= 23-2mi.
    // col = 8n + 2tig + 16mi - 48  (in [0,142] for valid slots; even -> st.64)
    #pragma unroll
    for (int mt = 0; mt < 2; ++mt) {
        const int mi = 2 * mh + mt;
        #pragma unroll
        for (int t = 0; t < 6; ++t) {
            const int n = 6 * ng + t;
            if (n >= 6 - 2 * mi && n <= 23 - 2 * mi) {
                const int col = 8 * n + 2 * tig + 16 * mi - 48;
                float* pA = sG + (16 * mi + gid) * SGP + col;
                float* pB = pA + 8 * SGP;
                *(float2*)pA = make_float2(acc[mt * 6 + t][0], acc[mt * 6 + t][1]);
                *(float2*)pB = make_float2(acc[mt * 6 + t][2], acc[mt * 6 + t][3]);
            }
        }
    }
    __syncthreads();                           // sG visible cross-warp

    // ---- Epilogue: out[i][j] = scores[i][j] (L2-hit LDG) + sG[i][j+15-(i&15)]
    // acc[] is dead here, so the score values borrow its registers: peak
    // pressure stays within the 85-reg occ-3 budget.
    #pragma unroll
    for (int k = 0; k < 8; ++k) {
        const int i = wid + 8 * k;
        const float* srow = scores + gbase + (size_t)i * S_LEN;
        const float* grow = sG + i * SGP + (15 - (i & 15));
        float* orow = out + gbase + (size_t)i * S_LEN;
        float sv[4];
        #pragma unroll
        for (int q = 0; q < 4; ++q)
            sv[q] = __ldg(srow + 32 * q + lane);
        #pragma unroll
        for (int q = 0; q < 4; ++q) {
            int j = 32 * q + lane;
            orow[j] = sv[q] + grow[j];
        }
    }
}

extern "C" void kernel_launch(void* const* d_in, const int* in_sizes, int n_in,
                              void* d_out, int out_size) {
    const float* query  = nullptr;  // 2*16*2048*64   = 4194304
    const float* scores = nullptr;  // 2*16*2048*2048 = 134217728
    const float* rel    = nullptr;  // 8192*64        = 524288
    for (int i = 0; i < n_in; ++i) {
        if (in_sizes[i] == 4194304)        query  = (const float*)d_in[i];
        else if (in_sizes[i] == 134217728) scores = (const float*)d_in[i];
        else if (in_sizes[i] == 524288)    rel    = (const float*)d_in[i];
    }

    // Pre-convert Q, E to fp16 scratch (every launch; deterministic)
    int convN = (Q_G4 + E_G4 + 255) / 256;
    convert_kernel<<<convN, 256>>>(query, rel);

    cudaFuncSetAttribute(relpos_mma,
                         cudaFuncAttributeMaxDynamicSharedMemorySize,
                         SMEM_BYTES);

    dim3 grid(S_LEN / TJ, S_LEN / TI, 32);  // (16, 32, B*H)
    relpos_mma<<<grid, 256, SMEM_BYTES>>>(scores, (float*)d_out);
}

// round 16
// speedup vs baseline: 1.0839x; 1.0839x over previous
#include <cuda_runtime.h>
#include <cuda_fp16.h>
#include <cstdint>

// out[b,h,i,j] = scores[b,h,i,j] + sum_d q[b,h,i,d] * E[(j-i)+4096, d]
// B=2,H=16,S=2048,D=64.
//
// 64x128 (i,j) tile. G[i,r] = Q(64x64) . E_rows(192x64)^T, j = r + i - 63.
// fp16 mma.sync m16n8k16, disjoint warp partition: warp (ng,mh) owns n-tiles
// [6ng,6ng+5] x m-tiles {2mh,2mh+1}; invalid slots computed (in-bounds reads)
// but never stored.
// R15 = best-of composition: R12 main kernel EXACTLY (fastest measured:
// TMA-staged scores into sS overlapping the mainloop, SMEM epilogue,
// occ 3, 80 regs) + R14's vectorized convert pre-kernel (10.4us -> 3.5us).
// R13/R14 established: scores must go TMA->SMEM->LDS (register prefetch
// kills occupancy; L2-prefetch+LDG exposes latency).

#define S_LEN 2048
#define TI 64
#define TJ 128
#define ER 192
#define PW 36            // Q/E pitch (u32); mainloop banks 4g+t bijective
#define SGP 148          // sG pitch (floats)
#define SSP 128          // sS pitch (floats), bulk dst rows contiguous

#define SMEM_S_U32   (TI * SSP)              // 8192
#define SMEM_QE_U32  (TI * PW + ER * PW)     // 9216
#define SMEM_G_U32   (TI * SGP)              // 9472 (aliases QE region)
#define SMEM_UNION_U32 (SMEM_G_U32 > SMEM_QE_U32 ? SMEM_G_U32 : SMEM_QE_U32)
#define SMEM_U32 (SMEM_S_U32 + SMEM_UNION_U32 + 8)
#define SMEM_BYTES (SMEM_U32 * 4)            // 70688

// fp16 scratch, pitch 36 u32/row (cols 32..35 pad, never read)
__device__ uint32_t g_qsc[32 * 2048 * PW];   // 9.4 MB
__device__ uint32_t g_esc[8192 * PW];        // 1.2 MB

__device__ __forceinline__ uint32_t smem_u32p(const void* p) {
    uint32_t a;
    asm("{ .reg .u64 t; cvta.to.shared.u64 t, %1; cvt.u32.u64 %0, t; }"
        : "=r"(a) : "l"(p));
    return a;
}

#define MBARRIER_INIT(mbar, cnt) \
    asm volatile("mbarrier.init.shared.b64 [%0], %1;" \
                 :: "r"((uint32_t)(mbar)), "r"((uint32_t)(cnt)) : "memory")
#define MBARRIER_EXPECT_TX(mbar, bytes) \
    asm volatile("mbarrier.arrive.expect_tx.shared.b64 _, [%0], %1;" \
                 :: "r"((uint32_t)(mbar)), "r"((uint32_t)(bytes)) : "memory")
#define MBARRIER_WAIT_PARITY(mbar, par) do {                                   \
    asm volatile(                                                              \
        "{\n\t.reg .pred P1;\n\t"                                              \
        "WAIT_LOOP_%=:\n\t"                                                    \
        "mbarrier.try_wait.parity.acquire.cta.shared::cta.b64 P1, [%0], %1, 0x989680;\n\t" \
        "@P1 bra.uni WAIT_DONE_%=;\n\t"                                        \
        "bra.uni WAIT_LOOP_%=;\n\t"                                            \
        "WAIT_DONE_%=:\n\t}"                                                   \
        :: "r"((uint32_t)(mbar)), "r"((uint32_t)(par)) : "memory");            \
} while (0)
#define FENCE_PROXY_ASYNC() asm volatile("fence.proxy.async.shared::cta;" ::: "memory")

#define BULK_G2S(dst, src, bytes, mbar) \
    asm volatile("cp.async.bulk.shared::cluster.global.mbarrier::complete_tx::bytes " \
                 "[%0], [%1], %2, [%3];" \
                 :: "r"((uint32_t)(dst)), "l"(src), "r"((uint32_t)(bytes)), \
                    "r"((uint32_t)(mbar)) : "memory")

__device__ __forceinline__ void mma_f16(float* c,
                                        uint32_t a0, uint32_t a1,
                                        uint32_t a2, uint32_t a3,
                                        uint32_t b0, uint32_t b1) {
    asm volatile(
        "mma.sync.aligned.m16n8k16.row.col.f32.f16.f16.f32 "
        "{%0,%1,%2,%3}, {%4,%5,%6,%7}, {%8,%9}, {%0,%1,%2,%3};"
        : "+f"(c[0]), "+f"(c[1]), "+f"(c[2]), "+f"(c[3])
        : "r"(a0), "r"(a1), "r"(a2), "r"(a3), "r"(b0), "r"(b1));
}

__device__ __forceinline__ uint32_t pack_h2(float lo, float hi) {
    __half2 h = __floats2half2_rn(lo, hi);
    return *(uint32_t*)&h;
}

// ---- Pre-kernel: fp32 -> fp16 scratch (pitch 36), vectorized x4 ----
#define Q_G4 (32 * 2048 * 8)   // groups of 4 u32 (8 halfs) for Q
#define E_G4 (8192 * 8)
__global__ __launch_bounds__(256)
void convert_kernel(const float* __restrict__ query,
                    const float* __restrict__ rel)
{
    int idx = blockIdx.x * 256 + threadIdx.x;
    if (idx < Q_G4) {
        int row = idx >> 3, c4 = (idx & 7) << 2;          // u32 col, x4
        const float* src = query + (size_t)row * 64 + (c4 << 1);
        float4 v0 = *(const float4*)(src);
        float4 v1 = *(const float4*)(src + 4);
        uint4 o;
        o.x = pack_h2(v0.x, v0.y); o.y = pack_h2(v0.z, v0.w);
        o.z = pack_h2(v1.x, v1.y); o.w = pack_h2(v1.z, v1.w);
        *(uint4*)(g_qsc + row * PW + c4) = o;
    } else if (idx < Q_G4 + E_G4) {
        int e = idx - Q_G4;
        int row = e >> 3, c4 = (e & 7) << 2;
        const float* src = rel + (size_t)row * 64 + (c4 << 1);
        float4 v0 = *(const float4*)(src);
        float4 v1 = *(const float4*)(src + 4);
        uint4 o;
        o.x = pack_h2(v0.x, v0.y); o.y = pack_h2(v0.z, v0.w);
        o.z = pack_h2(v1.x, v1.y); o.w = pack_h2(v1.z, v1.w);
        *(uint4*)(g_esc + row * PW + c4) = o;
    }
}

__global__ __launch_bounds__(256, 3)
void relpos_mma(const float* __restrict__ scores,
                float* __restrict__ out)
{
    extern __shared__ uint32_t smem[];
    float*    sS = (float*)smem;                   // [64][128] scores tile
    uint32_t* Qs = smem + SMEM_S_U32;              // [64][PW] packed half2
    uint32_t* Es = Qs + TI * PW;                   // [192][PW]
    float*    sG = (float*)(smem + SMEM_S_U32);    // [64][SGP] aliases Qs/Es
    uint32_t* bars = smem + SMEM_S_U32 + SMEM_UNION_U32;
    const uint32_t barQE = smem_u32p(bars);
    const uint32_t barS  = barQE + 8;

    const int tid  = threadIdx.x;
    const int wid  = tid >> 5;
    const int lane = tid & 31;
    const int gid  = lane >> 2;
    const int tig  = lane & 3;
    const int bh = blockIdx.z;
    const int i0 = blockIdx.y * TI;
    const int j0 = blockIdx.x * TJ;
    const size_t gbase = ((size_t)bh * S_LEN + i0) * S_LEN + j0;

    if (tid == 0) {
        MBARRIER_INIT(barQE, 1);
        MBARRIER_INIT(barS, 1);
        FENCE_PROXY_ASYNC();
        MBARRIER_EXPECT_TX(barQE, (TI + ER) * PW * 4);
        MBARRIER_EXPECT_TX(barS, TI * TJ * 4);
    }
    __syncthreads();   // barriers initialized before anyone waits

    if (tid == 0) {
        // Q + E tiles: single contiguous bulk copies from fp16 scratch
        const uint32_t* qsrc = g_qsc + ((size_t)bh * S_LEN + i0) * PW;
        BULK_G2S(smem_u32p(Qs), qsrc, TI * PW * 4, barQE);
        const int rBase = 4096 - 63 + (j0 - i0);   // [2049,5953]; +191 < 8192
        const uint32_t* esrc = g_esc + (size_t)rBase * PW;
        BULK_G2S(smem_u32p(Es), esrc, ER * PW * 4, barQE);
        // Scores tile: 64 row copies (512B each)
        const uint32_t sSaddr = smem_u32p(sS);
        const float* srow = scores + gbase;
        #pragma unroll 4
        for (int il = 0; il < TI; ++il)
            BULK_G2S(sSaddr + il * (SSP * 4), srow + (size_t)il * S_LEN,
                     TJ * 4, barS);
    }

    // ---- Wait Q/E, then band mainloop ----
    MBARRIER_WAIT_PARITY(barQE, 0);

    // warp (ng, mh): n-tiles 6ng..6ng+5, m-tiles {2mh, 2mh+1}
    const int ng = wid & 3;
    const int mh = wid >> 2;

    float acc[12][4];
    #pragma unroll
    for (int s = 0; s < 12; ++s) {
        acc[s][0] = 0.f; acc[s][1] = 0.f; acc[s][2] = 0.f; acc[s][3] = 0.f;
    }

    const uint32_t* aP0 = Qs + (32 * mh + gid) * PW + tig;       // m-tile 2mh
    const uint32_t* aP1 = aP0 + 16 * PW;                         // m-tile 2mh+1
    const uint32_t* bP  = Es + (48 * ng + gid) * PW + tig;

    #pragma unroll
    for (int k = 0; k < 4; ++k) {              // K = 64, 16 per MMA
        uint32_t a00 = aP0[0], a01 = aP0[8 * PW], a02 = aP0[4], a03 = aP0[8 * PW + 4];
        uint32_t a10 = aP1[0], a11 = aP1[8 * PW], a12 = aP1[4], a13 = aP1[8 * PW + 4];
        #pragma unroll
        for (int t = 0; t < 6; ++t) {
            const uint32_t* bp = bP + t * (8 * PW);
            uint32_t b0 = bp[0], b1 = bp[4];
            mma_f16(acc[t],     a00, a01, a02, a03, b0, b1);
            mma_f16(acc[6 + t], a10, a11, a12, a13, b0, b1);
        }
        aP0 += 8; aP1 += 8; bP += 8;           // +16 halfs
    }
    __syncthreads();                           // Q/E dead: sG may overwrite

    // ---- Band store (valid slots only; warp-uniform branch) ----
    // slot (mt, t): mi = 2mh+mt, n = 6ng+t; valid iff 6-2mi <= n <= 23-2mi.
    // col = 8n + 2tig + 16mi - 48  (in [0,142] for valid slots; even -> st.64)
    #pragma unroll
    for (int mt = 0; mt < 2; ++mt) {
        const int mi = 2 * mh + mt;
        #pragma unroll
        for (int t = 0; t < 6; ++t) {
            const int n = 6 * ng + t;
            if (n >= 6 - 2 * mi && n <= 23 - 2 * mi) {
                const int col = 8 * n + 2 * tig + 16 * mi - 48;
                float* pA = sG + (16 * mi + gid) * SGP + col;
                float* pB = pA + 8 * SGP;
                *(float2*)pA = make_float2(acc[mt * 6 + t][0], acc[mt * 6 + t][1]);
                *(float2*)pB = make_float2(acc[mt * 6 + t][2], acc[mt * 6 + t][3]);
            }
        }
    }
    MBARRIER_WAIT_PARITY(barS, 0);             // scores ready (usually no-op)
    __syncthreads();                           // sG visible cross-warp

    // ---- Epilogue: out[i][j] = sS[i][j] + sG[i][j + 15 - (i&15)] ----
    #pragma unroll
    for (int k = 0; k < 8; ++k) {
        const int i = wid + 8 * k;
        const float* srow = sS + i * SSP;
        const float* grow = sG + i * SGP + (15 - (i & 15));
        float* orow = out + gbase + (size_t)i * S_LEN;
        #pragma unroll
        for (int q = 0; q < 4; ++q) {
            int j = 32 * q + lane;
            orow[j] = srow[j] + grow[j];
        }
    }
}

extern "C" void kernel_launch(void* const* d_in, const int* in_sizes, int n_in,
                              void* d_out, int out_size) {
    const float* query  = nullptr;  // 2*16*2048*64   = 4194304
    const float* scores = nullptr;  // 2*16*2048*2048 = 134217728
    const float* rel    = nullptr;  // 8192*64        = 524288
    for (int i = 0; i < n_in; ++i) {
        if (in_sizes[i] == 4194304)        query  = (const float*)d_in[i];
        else if (in_sizes[i] == 134217728) scores = (const float*)d_in[i];
        else if (in_sizes[i] == 524288)    rel    = (const float*)d_in[i];
    }

    // Pre-convert Q, E to fp16 scratch (every launch; deterministic)
    int convN = (Q_G4 + E_G4 + 255) / 256;
    convert_kernel<<<convN, 256>>>(query, rel);

    cudaFuncSetAttribute(relpos_mma,
                         cudaFuncAttributeMaxDynamicSharedMemorySize,
                         SMEM_BYTES);

    dim3 grid(S_LEN / TJ, S_LEN / TI, 32);  // (16, 32, B*H)
    relpos_mma<<<grid, 256, SMEM_BYTES>>>(scores, (float*)d_out);
}